// round 11
// baseline (speedup 1.0000x reference)
#include <cuda_runtime.h>
#include <cuda_bf16.h>
#include <math.h>
#include <stdint.h>

#define NB 108
#define NN 392
#define NI 256
#define NH 4
#define NO 64
#define BNROWS (NB*NN)   /* 42336 */

typedef unsigned long long ull;

// ------------------------------ device scratch ------------------------------
static __device__ float g_mlp[(size_t)BNROWS * NI];
static __device__ float g_xp [(size_t)BNROWS * NI];
static __device__ float g_mk [NB * NI];
// pre-split / pre-transposed weights: [n=256][k=256] bf16, hi and lo parts
static __device__ __nv_bfloat16 g_BwH[65536];
static __device__ __nv_bfloat16 g_BwM[65536];
static __device__ __nv_bfloat16 g_BkH[65536];
static __device__ __nv_bfloat16 g_BkM[65536];

// ---- FMA-pipe exp / rcp (no MUFU) ------------------------------------------
__device__ __forceinline__ float fast_exp(float x) {
    float t = x * 1.44269504f;
    t = fminf(fmaxf(t, -125.0f), 125.0f);
    float fm = t + 12582912.0f;                      // round-to-nearest magic
    int   ni = __float_as_int(fm) - 0x4B400000;
    float f  = t - (fm - 12582912.0f);               // f in [-0.5, 0.5]
    float p  =              1.5403530e-4f;
    p = fmaf(p, f, 1.3333558e-3f);
    p = fmaf(p, f, 9.6181291e-3f);
    p = fmaf(p, f, 5.5504109e-2f);
    p = fmaf(p, f, 2.4022651e-1f);
    p = fmaf(p, f, 6.9314718e-1f);
    p = fmaf(p, f, 1.0f);
    return p * __int_as_float((ni + 127) << 23);
}
__device__ __forceinline__ float fast_rcp(float d) {
    float r = __int_as_float(0x7EF311C3 - __float_as_int(d));
    r = r * (2.0f - d * r);
    r = r * (2.0f - d * r);
    r = r * (2.0f - d * r);
    return r;
}
__device__ __forceinline__ float sigmoid_fast(float x) {
    return fast_rcp(1.0f + fast_exp(-x));
}
__device__ __forceinline__ float elu_fast(float x) {
    return x > 0.f ? x : (fast_exp(x) - 1.0f);
}

// ---- warp-level bf16 MMA (arch-generic, sm_80+) ----------------------------
__device__ __forceinline__ void mma16816(float* c, const uint32_t* a, const uint32_t* b) {
    asm volatile(
        "mma.sync.aligned.m16n8k16.row.col.f32.bf16.bf16.f32 "
        "{%0,%1,%2,%3}, {%4,%5,%6,%7}, {%8,%9}, {%0,%1,%2,%3};"
        : "+f"(c[0]), "+f"(c[1]), "+f"(c[2]), "+f"(c[3])
        : "r"(a[0]), "r"(a[1]), "r"(a[2]), "r"(a[3]), "r"(b[0]), "r"(b[1]));
}

__device__ __forceinline__ void split_bf16(float f0, float f1, uint32_t& hi, uint32_t& lo) {
    __nv_bfloat16 h0 = __float2bfloat16(f0);
    __nv_bfloat16 h1 = __float2bfloat16(f1);
    __nv_bfloat16 l0 = __float2bfloat16(f0 - __bfloat162float(h0));
    __nv_bfloat16 l1 = __float2bfloat16(f1 - __bfloat162float(h1));
    hi = ((uint32_t)__bfloat16_as_ushort(h1) << 16) | __bfloat16_as_ushort(h0);
    lo = ((uint32_t)__bfloat16_as_ushort(l1) << 16) | __bfloat16_as_ushort(l0);
}

// ---------------------------------------------------------------------------
// B prep: W[256,256] fp32 -> bf16 hi/lo, transposed to [n][k].
// ---------------------------------------------------------------------------
__global__ void __launch_bounds__(256)
bprep(const float* __restrict__ w, const float* __restrict__ kr)
{
    int t   = blockIdx.x * 256 + threadIdx.x;   // 0..131071
    int mat = t >> 16;
    int id  = t & 65535;
    int n   = id >> 8;
    int k   = id & 255;
    const float* src = mat ? kr : w;
    float v = src[(size_t)k * 256 + n];
    __nv_bfloat16 h = __float2bfloat16(v);
    __nv_bfloat16 l = __float2bfloat16(v - __bfloat162float(h));
    (mat ? g_BkH : g_BwH)[n * 256 + k] = h;
    (mat ? g_BkM : g_BwM)[n * 256 + k] = l;
}

// ---------------------------------------------------------------------------
// mma.sync GEMM: C[M,256] = epi( A[M,256] @ W[256,256] ), W pre-split [n][k].
// 3-pass bf16 split: Ah*Bh + Ah*Bl + Al*Bh.
// CTA 128 thr (2x2 warps), tile 64m x 128n, BK=32, padded smem pitch 40 bf16.
//   mode 0: sigmoid(acc + extra[col])
//   mode 3: 0.2*acc + extra[(row/392)*256 + col]
// ---------------------------------------------------------------------------
#define PITCH 40
__global__ void __launch_bounds__(128, 4)
gemm_mma(const float* __restrict__ A,
         const __nv_bfloat16* __restrict__ BH, const __nv_bfloat16* __restrict__ BL,
         const float* __restrict__ extra, float* __restrict__ C,
         int M, int mode)
{
    __shared__ __align__(16) __nv_bfloat16 sAh[64 * PITCH];
    __shared__ __align__(16) __nv_bfloat16 sAl[64 * PITCH];
    __shared__ __align__(16) __nv_bfloat16 sBh[128 * PITCH];
    __shared__ __align__(16) __nv_bfloat16 sBl[128 * PITCH];

    const int tid  = threadIdx.x;
    const int warp = tid >> 5, lane = tid & 31;
    const int g  = lane >> 2, tg = lane & 3;
    const int wm = warp >> 1, wn = warp & 1;
    const int rowBase = blockIdx.y * 64;
    const int colBase = blockIdx.x * 128;

    float c[2][8][4];
#pragma unroll
    for (int mt = 0; mt < 2; mt++)
#pragma unroll
        for (int nt = 0; nt < 8; nt++)
#pragma unroll
            for (int j = 0; j < 4; j++) c[mt][nt][j] = 0.f;

    const int r = tid >> 1, half = tid & 1;
    const int gr = rowBase + r;
    const float* aRow = A + (size_t)gr * 256 + half * 16;
    const __nv_bfloat16* bhRow = BH + (size_t)(colBase + tid) * 256;
    const __nv_bfloat16* blRow = BL + (size_t)(colBase + tid) * 256;

    for (int kc = 0; kc < 8; kc++) {
        {
            float f[16];
            if (gr < M) {
#pragma unroll
                for (int j = 0; j < 4; j++)
                    *(float4*)&f[4*j] = *(const float4*)(aRow + kc*32 + 4*j);
            } else {
#pragma unroll
                for (int j = 0; j < 16; j++) f[j] = 0.f;
            }
            __align__(16) uint32_t hv[8], lv[8];
#pragma unroll
            for (int j = 0; j < 8; j++)
                split_bf16(f[2*j], f[2*j+1], hv[j], lv[j]);
            int idx = r * PITCH + half * 16;
            *(uint4*)&sAh[idx]     = *(uint4*)&hv[0];
            *(uint4*)&sAh[idx + 8] = *(uint4*)&hv[4];
            *(uint4*)&sAl[idx]     = *(uint4*)&lv[0];
            *(uint4*)&sAl[idx + 8] = *(uint4*)&lv[4];
        }
        {
            int idx = tid * PITCH;
            const uint4* sh = (const uint4*)(bhRow + kc*32);
            const uint4* sl = (const uint4*)(blRow + kc*32);
#pragma unroll
            for (int j = 0; j < 4; j++) {
                *(uint4*)&sBh[idx + 8*j] = sh[j];
                *(uint4*)&sBl[idx + 8*j] = sl[j];
            }
        }
        __syncthreads();

#pragma unroll
        for (int ks = 0; ks < 32; ks += 16) {
            uint32_t bHf[8][2], bLf[8][2];
#pragma unroll
            for (int nt = 0; nt < 8; nt++) {
                int nb = (wn*64 + nt*8 + g) * PITCH + ks + tg*2;
                bHf[nt][0] = *(const uint32_t*)&sBh[nb];
                bHf[nt][1] = *(const uint32_t*)&sBh[nb + 8];
                bLf[nt][0] = *(const uint32_t*)&sBl[nb];
                bLf[nt][1] = *(const uint32_t*)&sBl[nb + 8];
            }
#pragma unroll
            for (int mt = 0; mt < 2; mt++) {
                int ab = (wm*32 + mt*16 + g) * PITCH + ks + tg*2;
                uint32_t aH[4], aL[4];
                aH[0] = *(const uint32_t*)&sAh[ab];
                aH[1] = *(const uint32_t*)&sAh[ab + 8*PITCH];
                aH[2] = *(const uint32_t*)&sAh[ab + 8];
                aH[3] = *(const uint32_t*)&sAh[ab + 8*PITCH + 8];
                aL[0] = *(const uint32_t*)&sAl[ab];
                aL[1] = *(const uint32_t*)&sAl[ab + 8*PITCH];
                aL[2] = *(const uint32_t*)&sAl[ab + 8];
                aL[3] = *(const uint32_t*)&sAl[ab + 8*PITCH + 8];
#pragma unroll
                for (int nt = 0; nt < 8; nt++) {
                    mma16816(c[mt][nt], aH, bHf[nt]);
                    mma16816(c[mt][nt], aH, bLf[nt]);
                    mma16816(c[mt][nt], aL, bHf[nt]);
                }
            }
        }
        __syncthreads();
    }

#pragma unroll
    for (int mt = 0; mt < 2; mt++) {
#pragma unroll
        for (int rr = 0; rr < 2; rr++) {
            int orow = rowBase + wm*32 + mt*16 + g + rr*8;
            if (orow >= M) continue;
            int bb = orow / NN;
            const float* mkp = extra + (size_t)bb * 256;
#pragma unroll
            for (int nt = 0; nt < 8; nt++) {
                int col = colBase + wn*64 + nt*8 + tg*2;
                float v0 = c[mt][nt][rr*2];
                float v1 = c[mt][nt][rr*2 + 1];
                if (mode == 0) {
                    v0 = sigmoid_fast(v0 + extra[col]);
                    v1 = sigmoid_fast(v1 + extra[col + 1]);
                } else {
                    float2 m2 = *(const float2*)(mkp + col);
                    v0 = 0.2f * v0 + m2.x;
                    v1 = 0.2f * v1 + m2.y;
                }
                float2 o; o.x = v0; o.y = v1;
                *(float2*)(C + (size_t)orow * 256 + col) = o;
            }
        }
    }
}

// ---------------------------------------------------------------------------
// Per-batch column mean of mlp (x 0.8/392) through `kernel`.
// ---------------------------------------------------------------------------
__global__ void __launch_bounds__(512)
mean_meank(const float* __restrict__ mlp, const float* __restrict__ ker,
           float* __restrict__ meanK)
{
    __shared__ float part[2][256];
    __shared__ float meanS[256];
    const int b = blockIdx.x;
    const int f    = threadIdx.x & 255;
    const int half = threadIdx.x >> 8;

    const float* base = mlp + (size_t)b * NN * 256 + f;
    float s0 = 0.f, s1 = 0.f, s2 = 0.f, s3 = 0.f;
    const int n0 = half * 196;
    for (int n = n0; n < n0 + 196; n += 4) {
        s0 += base[(size_t)(n+0) * 256];
        s1 += base[(size_t)(n+1) * 256];
        s2 += base[(size_t)(n+2) * 256];
        s3 += base[(size_t)(n+3) * 256];
    }
    part[half][f] = (s0 + s1) + (s2 + s3);
    __syncthreads();
    if (half == 0)
        meanS[f] = (part[0][f] + part[1][f]) * (0.8f / 392.0f);
    __syncthreads();

    float acc = 0.f;
    const int f0 = half * 128;
    for (int ff = f0; ff < f0 + 128; ff++)
        acc += meanS[ff] * ker[(size_t)ff * 256 + f];
    __syncthreads();
    part[half][f] = acc;
    __syncthreads();
    if (half == 0)
        meanK[(size_t)b * 256 + f] = part[0][f] + part[1][f];
}

// ---------------------------------------------------------------------------
// Attention via sorted-threshold sweep. One block per (h, b), 448 threads.
//
// P[n,m] = exp(leaky(s_n+ng_m) - ref_n). Splitting by sign of (s_n+ng_m):
//   pos (ng_m > -s_n): w+_n * exp(ng_m - Mx)
//   neg (ng_m <= -s_n): w-_n * exp(0.2(ng_m - Mx))
// Sort m by ng; per row the boundary is a threshold index t_n. Then
//   out[n,:] = w+_n * SuffixPos[t_n] + w-_n * PrefixNeg[t_n]
// computed by a single sweep with running vector sums (O(N*O) not O(N^2*O)).
// s/ng computed locally from the staged V slice (sng kernel deleted).
// ---------------------------------------------------------------------------
#define ATHR 448
__global__ void __launch_bounds__(ATHR)
attn_sweep(const float* __restrict__ xp, const float* __restrict__ ask,
           const float* __restrict__ ank, const float* __restrict__ bias,
           float* __restrict__ out)
{
    const int h = blockIdx.x;
    const int b = blockIdx.y;
    const int tid  = threadIdx.x;
    const int wId  = tid >> 5, lane = tid & 31;
    const int g    = tid >> 6, o = tid & 63;     // 7 groups x 64 cols

    extern __shared__ float Vs[];                // [392][64]
    __shared__ float ngS[NN], sS[NN];
    __shared__ float sortNg[NN];
    __shared__ float ePs[NN], eNs[NN];
    __shared__ float EpreP[NN+1], EpreN[NN+1];
    __shared__ float wpS[NN], wnS[NN];
    __shared__ short sIdx[NN], tS[NN], rowOrd[NN];
    __shared__ int   hist[NN+1], base[NN+2], cursor[NN+1];
    __shared__ float segP[ATHR], segN[ATHR];
    __shared__ float askS[64], ankS[64], biasS[64];
    __shared__ float red[14];
    __shared__ float MxSh;

    if (tid < 64) {
        askS[tid]  = ask [tid * NH + h];
        ankS[tid]  = ank [tid * NH + h];
        biasS[tid] = bias[h * 64 + tid];
    }
    if (tid < NN + 1) hist[tid] = 0;

    // ---- stage V = xp[b, :, h*64 : h*64+64] into smem ----
    const float* Vg = xp + (size_t)b * NN * 256 + h * 64;
    for (int m = g; m < NN; m += 7)
        Vs[m * 64 + o] = Vg[(size_t)m * 256 + o];
    __syncthreads();

    // ---- s/ng from staged V (one warp per row group) ----
    for (int rr = wId; rr < NN; rr += 14) {
        float v0 = Vs[rr*64 + lane], v1 = Vs[rr*64 + 32 + lane];
        float sv = v0 * askS[lane] + v1 * askS[lane + 32];
        float nv = v0 * ankS[lane] + v1 * ankS[lane + 32];
#pragma unroll
        for (int off = 16; off; off >>= 1) {
            sv += __shfl_xor_sync(0xffffffffu, sv, off);
            nv += __shfl_xor_sync(0xffffffffu, nv, off);
        }
        if (lane == 0) { sS[rr] = sv; ngS[rr] = nv; }
    }
    __syncthreads();

    // ---- Mx = max ng ----
    float mv = (tid < NN) ? ngS[tid] : -1e30f;
#pragma unroll
    for (int off = 16; off; off >>= 1)
        mv = fmaxf(mv, __shfl_xor_sync(0xffffffffu, mv, off));
    if (lane == 0) red[wId] = mv;
    __syncthreads();
    if (tid == 0) {
        float m2 = red[0];
#pragma unroll
        for (int i = 1; i < 14; i++) m2 = fmaxf(m2, red[i]);
        MxSh = m2;
    }
    __syncthreads();
    const float Mx = MxSh;

    // ---- rank-sort m by ng, exp tables ----
    if (tid < NN) {
        float v = ngS[tid];
        int rank = 0;
        for (int j = 0; j < NN; j++) {
            float u = ngS[j];
            rank += (u < v) || (u == v && j < tid);
        }
        sortNg[rank] = v;
        sIdx[rank]   = (short)tid;
        ePs[rank]    = __expf(v - Mx);
        eNs[rank]    = __expf(0.2f * (v - Mx));
    }
    __syncthreads();

    // ---- scalar prefix sums (two independent threads, unroll-4 chains) ----
    if (tid == 0) {
        float rsum = 0.f; EpreP[0] = 0.f;
        for (int j = 0; j < NN; j += 4) {
            float a0 = ePs[j], a1 = ePs[j+1], a2 = ePs[j+2], a3 = ePs[j+3];
            float s1 = a0+a1, s2 = s1+a2, s3 = s2+a3;
            EpreP[j+1] = rsum + a0; EpreP[j+2] = rsum + s1;
            EpreP[j+3] = rsum + s2; rsum += s3; EpreP[j+4] = rsum;
        }
    } else if (tid == 32) {
        float rsum = 0.f; EpreN[0] = 0.f;
        for (int j = 0; j < NN; j += 4) {
            float a0 = eNs[j], a1 = eNs[j+1], a2 = eNs[j+2], a3 = eNs[j+3];
            float s1 = a0+a1, s2 = s1+a2, s3 = s2+a3;
            EpreN[j+1] = rsum + a0; EpreN[j+2] = rsum + s1;
            EpreN[j+3] = rsum + s2; rsum += s3; EpreN[j+4] = rsum;
        }
    }
    __syncthreads();

    // ---- per-row threshold, weights, denominator ----
    if (tid < NN) {
        float sn = sS[tid];
        float v = -sn;
        int lo = 0, hi = NN;
        while (lo < hi) { int mid = (lo + hi) >> 1; if (sortNg[mid] <= v) lo = mid + 1; else hi = mid; }
        int t = lo;                                  // #{ng <= -s_n}
        float sm  = sn + Mx;
        float ref = sm > 0.f ? sm : 0.2f * sm;
        float wp  = __expf(sm - ref);                // <= 1
        float wn  = __expf(0.2f * sm - ref);         // <= 1
        float denom = wp * (EpreP[NN] - EpreP[t]) + wn * EpreN[t];
        float inv = 1.0f / denom;
        wpS[tid] = wp * inv;
        wnS[tid] = wn * inv;
        tS[tid]  = (short)t;
        atomicAdd(&hist[t], 1);
    }
    __syncthreads();
    if (tid == 0) {
        int rsum = 0;
        for (int j = 0; j <= NN; j++) { base[j] = rsum; rsum += hist[j]; }
        base[NN + 1] = rsum;
    }
    __syncthreads();
    if (tid < NN + 1) cursor[tid] = base[tid];
    __syncthreads();
    if (tid < NN) {
        int pos = atomicAdd(&cursor[tS[tid]], 1);
        rowOrd[pos] = (short)tid;
    }

    // ---- per-segment partial sums (7 segments x 56) ----
    {
        float pP = 0.f, pN = 0.f;
        const int j0 = g * 56;
        for (int j = j0; j < j0 + 56; j++) {
            float v = Vs[(int)sIdx[j] * 64 + o];
            pP = fmaf(ePs[j], v, pP);
            pN = fmaf(eNs[j], v, pN);
        }
        segP[g * 64 + o] = pP;
        segN[g * 64 + o] = pN;
    }
    __syncthreads();

    // ---- segment start states ----
    float Spos = 0.f, Pneg = 0.f;
    {
        float tot = 0.f, sub = 0.f;
#pragma unroll
        for (int gg = 0; gg < 7; gg++) {
            float vP = segP[gg * 64 + o];
            tot += vP;
            if (gg < g) { sub += vP; Pneg += segN[gg * 64 + o]; }
        }
        Spos = tot - sub;
    }

    // ---- sweep: output buckets, update running sums ----
    const float biasO = biasS[o];
    float* outBase = out + (size_t)b * NN * 256 + h * 64 + o;
    const int j0 = g * 56;
    for (int j = j0; j < j0 + 56; j++) {
        for (int rr = base[j]; rr < base[j+1]; rr++) {
            int n = rowOrd[rr];
            float val = wpS[n] * Spos + wnS[n] * Pneg + biasO;
            outBase[(size_t)n * 256] = elu_fast(val);
        }
        float v = Vs[(int)sIdx[j] * 64 + o];
        Pneg = fmaf(eNs[j], v, Pneg);
        Spos = fmaf(-ePs[j], v, Spos);
    }
    if (g == 6) {   // bucket t = 392 (all-negative rows)
        for (int rr = base[NN]; rr < base[NN+1]; rr++) {
            int n = rowOrd[rr];
            float val = wpS[n] * Spos + wnS[n] * Pneg + biasO;
            outBase[(size_t)n * 256] = elu_fast(val);
        }
    }
}

// ---------------------------------------------------------------------------
extern "C" void kernel_launch(void* const* d_in, const int* in_sizes, int n_in,
                              void* d_out, int out_size)
{
    const float* x    = (const float*)d_in[0];   // [B,N,I]
    const float* wml  = (const float*)d_in[2];   // [I,I]
    const float* bml  = (const float*)d_in[3];   // [I]
    const float* ker  = (const float*)d_in[4];   // [I,H,O]
    const float* ask  = (const float*)d_in[5];   // [O,H,1]
    const float* ank  = (const float*)d_in[6];   // [O,H,1]
    const float* bias = (const float*)d_in[7];   // [H*O]
    float* out = (float*)d_out;

    float *p_mlp, *p_xp, *p_mk;
    __nv_bfloat16 *p_bwH, *p_bwM, *p_bkH, *p_bkM;
    cudaGetSymbolAddress((void**)&p_mlp, g_mlp);
    cudaGetSymbolAddress((void**)&p_xp,  g_xp);
    cudaGetSymbolAddress((void**)&p_mk,  g_mk);
    cudaGetSymbolAddress((void**)&p_bwH, g_BwH);
    cudaGetSymbolAddress((void**)&p_bwM, g_BwM);
    cudaGetSymbolAddress((void**)&p_bkH, g_BkH);
    cudaGetSymbolAddress((void**)&p_bkM, g_BkM);

    const int MT = (BNROWS + 63) / 64;           // 662
    const int VSMEM = NN * 64 * sizeof(float);   // 100352
    cudaFuncSetAttribute(attn_sweep, cudaFuncAttributeMaxDynamicSharedMemorySize, VSMEM);

    // 0) split + transpose both weight matrices to [n][k] bf16 hi/lo
    bprep<<<512, 256>>>(wml, ker);

    // 1) mlp = sigmoid(x @ w_mlp + b_mlp)   [mma.sync bf16 3-pass]
    gemm_mma<<<dim3(2, MT), 128>>>(x, p_bwH, p_bwM, bml, p_mlp, BNROWS, 0);

    // 2) APPNP rank-1 (a == ones/N): meanK[b] = (0.8/N * sum_n mlp[b,n]) @ kernel
    mean_meank<<<NB, 512>>>(p_mlp, ker, p_mk);

    // 3) xp = 0.2*(mlp @ kernel) + meanK[b]
    gemm_mma<<<dim3(2, MT), 128>>>(p_mlp, p_bkH, p_bkM, p_mk, p_xp, BNROWS, 3);

    // 4) attention: sorted-threshold sweep (softmax + PV + bias + ELU + s/ng)
    attn_sweep<<<dim3(NH, NB), ATHR, VSMEM>>>(p_xp, ask, ank, bias, out);
}

// round 12
// speedup vs baseline: 1.0017x; 1.0017x over previous
#include <cuda_runtime.h>
#include <cuda_bf16.h>
#include <math.h>
#include <stdint.h>

#define NB 108
#define NN 392
#define NI 256
#define NH 4
#define NO 64
#define BNROWS (NB*NN)   /* 42336 */

typedef unsigned long long ull;

// ------------------------------ device scratch ------------------------------
static __device__ float g_mlp[(size_t)BNROWS * NI];
static __device__ float g_xp [(size_t)BNROWS * NI];
static __device__ float g_mk [NB * NI];
// pre-split / pre-transposed weights: [n=256][k=256] bf16, hi and lo parts
static __device__ __nv_bfloat16 g_BwH[65536];
static __device__ __nv_bfloat16 g_BwM[65536];
static __device__ __nv_bfloat16 g_BkH[65536];
static __device__ __nv_bfloat16 g_BkM[65536];

// ---- FMA-pipe exp / rcp (no MUFU) ------------------------------------------
__device__ __forceinline__ float fast_exp(float x) {
    float t = x * 1.44269504f;
    t = fminf(fmaxf(t, -125.0f), 125.0f);
    float fm = t + 12582912.0f;                      // round-to-nearest magic
    int   ni = __float_as_int(fm) - 0x4B400000;
    float f  = t - (fm - 12582912.0f);               // f in [-0.5, 0.5]
    float p  =              1.5403530e-4f;
    p = fmaf(p, f, 1.3333558e-3f);
    p = fmaf(p, f, 9.6181291e-3f);
    p = fmaf(p, f, 5.5504109e-2f);
    p = fmaf(p, f, 2.4022651e-1f);
    p = fmaf(p, f, 6.9314718e-1f);
    p = fmaf(p, f, 1.0f);
    return p * __int_as_float((ni + 127) << 23);
}
__device__ __forceinline__ float fast_rcp(float d) {
    float r = __int_as_float(0x7EF311C3 - __float_as_int(d));
    r = r * (2.0f - d * r);
    r = r * (2.0f - d * r);
    r = r * (2.0f - d * r);
    return r;
}
__device__ __forceinline__ float sigmoid_fast(float x) {
    return fast_rcp(1.0f + fast_exp(-x));
}
__device__ __forceinline__ float elu_fast(float x) {
    return x > 0.f ? x : (fast_exp(x) - 1.0f);
}

// ---- warp-level bf16 MMA (arch-generic, sm_80+) ----------------------------
__device__ __forceinline__ void mma16816(float* c, const uint32_t* a, const uint32_t* b) {
    asm volatile(
        "mma.sync.aligned.m16n8k16.row.col.f32.bf16.bf16.f32 "
        "{%0,%1,%2,%3}, {%4,%5,%6,%7}, {%8,%9}, {%0,%1,%2,%3};"
        : "+f"(c[0]), "+f"(c[1]), "+f"(c[2]), "+f"(c[3])
        : "r"(a[0]), "r"(a[1]), "r"(a[2]), "r"(a[3]), "r"(b[0]), "r"(b[1]));
}

__device__ __forceinline__ void split_bf16(float f0, float f1, uint32_t& hi, uint32_t& lo) {
    __nv_bfloat16 h0 = __float2bfloat16(f0);
    __nv_bfloat16 h1 = __float2bfloat16(f1);
    __nv_bfloat16 l0 = __float2bfloat16(f0 - __bfloat162float(h0));
    __nv_bfloat16 l1 = __float2bfloat16(f1 - __bfloat162float(h1));
    hi = ((uint32_t)__bfloat16_as_ushort(h1) << 16) | __bfloat16_as_ushort(h0);
    lo = ((uint32_t)__bfloat16_as_ushort(l1) << 16) | __bfloat16_as_ushort(l0);
}

// ---------------------------------------------------------------------------
// B prep: W[256,256] fp32 -> bf16 hi/lo, transposed to [n][k].
// ---------------------------------------------------------------------------
__global__ void __launch_bounds__(256)
bprep(const float* __restrict__ w, const float* __restrict__ kr)
{
    int t   = blockIdx.x * 256 + threadIdx.x;   // 0..131071
    int mat = t >> 16;
    int id  = t & 65535;
    int n   = id >> 8;
    int k   = id & 255;
    const float* src = mat ? kr : w;
    float v = src[(size_t)k * 256 + n];
    __nv_bfloat16 h = __float2bfloat16(v);
    __nv_bfloat16 l = __float2bfloat16(v - __bfloat162float(h));
    (mat ? g_BkH : g_BwH)[n * 256 + k] = h;
    (mat ? g_BkM : g_BwM)[n * 256 + k] = l;
}

// ---------------------------------------------------------------------------
// mma.sync GEMM: C[M,256] = epi( A[M,256] @ W[256,256] ), W pre-split [n][k].
// 3-pass bf16 split: Ah*Bh + Ah*Bl + Al*Bh.
// CTA 128 thr (2x2 warps), tile 64m x 128n, BK=32, padded smem pitch 40 bf16.
//   mode 0: sigmoid(acc + extra[col])
//   mode 3: 0.2*acc + extra[(row/392)*256 + col]
// ---------------------------------------------------------------------------
#define PITCH 40
__global__ void __launch_bounds__(128, 4)
gemm_mma(const float* __restrict__ A,
         const __nv_bfloat16* __restrict__ BH, const __nv_bfloat16* __restrict__ BL,
         const float* __restrict__ extra, float* __restrict__ C,
         int M, int mode)
{
    __shared__ __align__(16) __nv_bfloat16 sAh[64 * PITCH];
    __shared__ __align__(16) __nv_bfloat16 sAl[64 * PITCH];
    __shared__ __align__(16) __nv_bfloat16 sBh[128 * PITCH];
    __shared__ __align__(16) __nv_bfloat16 sBl[128 * PITCH];

    const int tid  = threadIdx.x;
    const int warp = tid >> 5, lane = tid & 31;
    const int g  = lane >> 2, tg = lane & 3;
    const int wm = warp >> 1, wn = warp & 1;
    const int rowBase = blockIdx.y * 64;
    const int colBase = blockIdx.x * 128;

    float c[2][8][4];
#pragma unroll
    for (int mt = 0; mt < 2; mt++)
#pragma unroll
        for (int nt = 0; nt < 8; nt++)
#pragma unroll
            for (int j = 0; j < 4; j++) c[mt][nt][j] = 0.f;

    const int r = tid >> 1, half = tid & 1;
    const int gr = rowBase + r;
    const float* aRow = A + (size_t)gr * 256 + half * 16;
    const __nv_bfloat16* bhRow = BH + (size_t)(colBase + tid) * 256;
    const __nv_bfloat16* blRow = BL + (size_t)(colBase + tid) * 256;

    for (int kc = 0; kc < 8; kc++) {
        {
            float f[16];
            if (gr < M) {
#pragma unroll
                for (int j = 0; j < 4; j++)
                    *(float4*)&f[4*j] = *(const float4*)(aRow + kc*32 + 4*j);
            } else {
#pragma unroll
                for (int j = 0; j < 16; j++) f[j] = 0.f;
            }
            __align__(16) uint32_t hv[8], lv[8];
#pragma unroll
            for (int j = 0; j < 8; j++)
                split_bf16(f[2*j], f[2*j+1], hv[j], lv[j]);
            int idx = r * PITCH + half * 16;
            *(uint4*)&sAh[idx]     = *(uint4*)&hv[0];
            *(uint4*)&sAh[idx + 8] = *(uint4*)&hv[4];
            *(uint4*)&sAl[idx]     = *(uint4*)&lv[0];
            *(uint4*)&sAl[idx + 8] = *(uint4*)&lv[4];
        }
        {
            int idx = tid * PITCH;
            const uint4* sh = (const uint4*)(bhRow + kc*32);
            const uint4* sl = (const uint4*)(blRow + kc*32);
#pragma unroll
            for (int j = 0; j < 4; j++) {
                *(uint4*)&sBh[idx + 8*j] = sh[j];
                *(uint4*)&sBl[idx + 8*j] = sl[j];
            }
        }
        __syncthreads();

#pragma unroll
        for (int ks = 0; ks < 32; ks += 16) {
            uint32_t bHf[8][2], bLf[8][2];
#pragma unroll
            for (int nt = 0; nt < 8; nt++) {
                int nb = (wn*64 + nt*8 + g) * PITCH + ks + tg*2;
                bHf[nt][0] = *(const uint32_t*)&sBh[nb];
                bHf[nt][1] = *(const uint32_t*)&sBh[nb + 8];
                bLf[nt][0] = *(const uint32_t*)&sBl[nb];
                bLf[nt][1] = *(const uint32_t*)&sBl[nb + 8];
            }
#pragma unroll
            for (int mt = 0; mt < 2; mt++) {
                int ab = (wm*32 + mt*16 + g) * PITCH + ks + tg*2;
                uint32_t aH[4], aL[4];
                aH[0] = *(const uint32_t*)&sAh[ab];
                aH[1] = *(const uint32_t*)&sAh[ab + 8*PITCH];
                aH[2] = *(const uint32_t*)&sAh[ab + 8];
                aH[3] = *(const uint32_t*)&sAh[ab + 8*PITCH + 8];
                aL[0] = *(const uint32_t*)&sAl[ab];
                aL[1] = *(const uint32_t*)&sAl[ab + 8*PITCH];
                aL[2] = *(const uint32_t*)&sAl[ab + 8];
                aL[3] = *(const uint32_t*)&sAl[ab + 8*PITCH + 8];
#pragma unroll
                for (int nt = 0; nt < 8; nt++) {
                    mma16816(c[mt][nt], aH, bHf[nt]);
                    mma16816(c[mt][nt], aH, bLf[nt]);
                    mma16816(c[mt][nt], aL, bHf[nt]);
                }
            }
        }
        __syncthreads();
    }

#pragma unroll
    for (int mt = 0; mt < 2; mt++) {
#pragma unroll
        for (int rr = 0; rr < 2; rr++) {
            int orow = rowBase + wm*32 + mt*16 + g + rr*8;
            if (orow >= M) continue;
            int bb = orow / NN;
            const float* mkp = extra + (size_t)bb * 256;
#pragma unroll
            for (int nt = 0; nt < 8; nt++) {
                int col = colBase + wn*64 + nt*8 + tg*2;
                float v0 = c[mt][nt][rr*2];
                float v1 = c[mt][nt][rr*2 + 1];
                if (mode == 0) {
                    v0 = sigmoid_fast(v0 + extra[col]);
                    v1 = sigmoid_fast(v1 + extra[col + 1]);
                } else {
                    float2 m2 = *(const float2*)(mkp + col);
                    v0 = 0.2f * v0 + m2.x;
                    v1 = 0.2f * v1 + m2.y;
                }
                float2 o; o.x = v0; o.y = v1;
                *(float2*)(C + (size_t)orow * 256 + col) = o;
            }
        }
    }
}

// ---------------------------------------------------------------------------
// Per-batch column mean of mlp (x 0.8/392) through `kernel`.
// ---------------------------------------------------------------------------
__global__ void __launch_bounds__(512)
mean_meank(const float* __restrict__ mlp, const float* __restrict__ ker,
           float* __restrict__ meanK)
{
    __shared__ float part[2][256];
    __shared__ float meanS[256];
    const int b = blockIdx.x;
    const int f    = threadIdx.x & 255;
    const int half = threadIdx.x >> 8;

    const float* base = mlp + (size_t)b * NN * 256 + f;
    float s0 = 0.f, s1 = 0.f, s2 = 0.f, s3 = 0.f;
    const int n0 = half * 196;
    for (int n = n0; n < n0 + 196; n += 4) {
        s0 += base[(size_t)(n+0) * 256];
        s1 += base[(size_t)(n+1) * 256];
        s2 += base[(size_t)(n+2) * 256];
        s3 += base[(size_t)(n+3) * 256];
    }
    part[half][f] = (s0 + s1) + (s2 + s3);
    __syncthreads();
    if (half == 0)
        meanS[f] = (part[0][f] + part[1][f]) * (0.8f / 392.0f);
    __syncthreads();

    float acc = 0.f;
    const int f0 = half * 128;
    for (int ff = f0; ff < f0 + 128; ff++)
        acc += meanS[ff] * ker[(size_t)ff * 256 + f];
    __syncthreads();
    part[half][f] = acc;
    __syncthreads();
    if (half == 0)
        meanK[(size_t)b * 256 + f] = part[0][f] + part[1][f];
}

// ---------------------------------------------------------------------------
// Attention via sorted-threshold sweep. One block per (h, b), 448 threads.
//
// P[n,m] = exp(leaky(s_n+ng_m) - ref_n). Splitting by sign of (s_n+ng_m):
//   pos (ng_m > -s_n): w+_n * exp(ng_m - Mx)
//   neg (ng_m <= -s_n): w-_n * exp(0.2(ng_m - Mx))
// Sort m by ng; per row the boundary is a threshold index t_n. Then
//   out[n,:] = w+_n * SuffixPos[t_n] + w-_n * PrefixNeg[t_n]
// computed by a single sweep with running vector sums (O(N*O) not O(N^2*O)).
// s/ng computed locally from the staged V slice (sng kernel deleted).
// ---------------------------------------------------------------------------
#define ATHR 448
__global__ void __launch_bounds__(ATHR)
attn_sweep(const float* __restrict__ xp, const float* __restrict__ ask,
           const float* __restrict__ ank, const float* __restrict__ bias,
           float* __restrict__ out)
{
    const int h = blockIdx.x;
    const int b = blockIdx.y;
    const int tid  = threadIdx.x;
    const int wId  = tid >> 5, lane = tid & 31;
    const int g    = tid >> 6, o = tid & 63;     // 7 groups x 64 cols

    extern __shared__ float Vs[];                // [392][64]
    __shared__ float ngS[NN], sS[NN];
    __shared__ float sortNg[NN];
    __shared__ float ePs[NN], eNs[NN];
    __shared__ float EpreP[NN+1], EpreN[NN+1];
    __shared__ float wpS[NN], wnS[NN];
    __shared__ short sIdx[NN], tS[NN], rowOrd[NN];
    __shared__ int   hist[NN+1], base[NN+2], cursor[NN+1];
    __shared__ float segP[ATHR], segN[ATHR];
    __shared__ float askS[64], ankS[64], biasS[64];
    __shared__ float red[14];
    __shared__ float MxSh;

    if (tid < 64) {
        askS[tid]  = ask [tid * NH + h];
        ankS[tid]  = ank [tid * NH + h];
        biasS[tid] = bias[h * 64 + tid];
    }
    if (tid < NN + 1) hist[tid] = 0;

    // ---- stage V = xp[b, :, h*64 : h*64+64] into smem ----
    const float* Vg = xp + (size_t)b * NN * 256 + h * 64;
    for (int m = g; m < NN; m += 7)
        Vs[m * 64 + o] = Vg[(size_t)m * 256 + o];
    __syncthreads();

    // ---- s/ng from staged V (one warp per row group) ----
    for (int rr = wId; rr < NN; rr += 14) {
        float v0 = Vs[rr*64 + lane], v1 = Vs[rr*64 + 32 + lane];
        float sv = v0 * askS[lane] + v1 * askS[lane + 32];
        float nv = v0 * ankS[lane] + v1 * ankS[lane + 32];
#pragma unroll
        for (int off = 16; off; off >>= 1) {
            sv += __shfl_xor_sync(0xffffffffu, sv, off);
            nv += __shfl_xor_sync(0xffffffffu, nv, off);
        }
        if (lane == 0) { sS[rr] = sv; ngS[rr] = nv; }
    }
    __syncthreads();

    // ---- Mx = max ng ----
    float mv = (tid < NN) ? ngS[tid] : -1e30f;
#pragma unroll
    for (int off = 16; off; off >>= 1)
        mv = fmaxf(mv, __shfl_xor_sync(0xffffffffu, mv, off));
    if (lane == 0) red[wId] = mv;
    __syncthreads();
    if (tid == 0) {
        float m2 = red[0];
#pragma unroll
        for (int i = 1; i < 14; i++) m2 = fmaxf(m2, red[i]);
        MxSh = m2;
    }
    __syncthreads();
    const float Mx = MxSh;

    // ---- rank-sort m by ng, exp tables ----
    if (tid < NN) {
        float v = ngS[tid];
        int rank = 0;
        for (int j = 0; j < NN; j++) {
            float u = ngS[j];
            rank += (u < v) || (u == v && j < tid);
        }
        sortNg[rank] = v;
        sIdx[rank]   = (short)tid;
        ePs[rank]    = __expf(v - Mx);
        eNs[rank]    = __expf(0.2f * (v - Mx));
    }
    __syncthreads();

    // ---- scalar prefix sums (two independent threads, unroll-4 chains) ----
    if (tid == 0) {
        float rsum = 0.f; EpreP[0] = 0.f;
        for (int j = 0; j < NN; j += 4) {
            float a0 = ePs[j], a1 = ePs[j+1], a2 = ePs[j+2], a3 = ePs[j+3];
            float s1 = a0+a1, s2 = s1+a2, s3 = s2+a3;
            EpreP[j+1] = rsum + a0; EpreP[j+2] = rsum + s1;
            EpreP[j+3] = rsum + s2; rsum += s3; EpreP[j+4] = rsum;
        }
    } else if (tid == 32) {
        float rsum = 0.f; EpreN[0] = 0.f;
        for (int j = 0; j < NN; j += 4) {
            float a0 = eNs[j], a1 = eNs[j+1], a2 = eNs[j+2], a3 = eNs[j+3];
            float s1 = a0+a1, s2 = s1+a2, s3 = s2+a3;
            EpreN[j+1] = rsum + a0; EpreN[j+2] = rsum + s1;
            EpreN[j+3] = rsum + s2; rsum += s3; EpreN[j+4] = rsum;
        }
    }
    __syncthreads();

    // ---- per-row threshold, weights, denominator ----
    if (tid < NN) {
        float sn = sS[tid];
        float v = -sn;
        int lo = 0, hi = NN;
        while (lo < hi) { int mid = (lo + hi) >> 1; if (sortNg[mid] <= v) lo = mid + 1; else hi = mid; }
        int t = lo;                                  // #{ng <= -s_n}
        float sm  = sn + Mx;
        float ref = sm > 0.f ? sm : 0.2f * sm;
        float wp  = __expf(sm - ref);                // <= 1
        float wn  = __expf(0.2f * sm - ref);         // <= 1
        float denom = wp * (EpreP[NN] - EpreP[t]) + wn * EpreN[t];
        float inv = 1.0f / denom;
        wpS[tid] = wp * inv;
        wnS[tid] = wn * inv;
        tS[tid]  = (short)t;
        atomicAdd(&hist[t], 1);
    }
    __syncthreads();
    if (tid == 0) {
        int rsum = 0;
        for (int j = 0; j <= NN; j++) { base[j] = rsum; rsum += hist[j]; }
        base[NN + 1] = rsum;
    }
    __syncthreads();
    if (tid < NN + 1) cursor[tid] = base[tid];
    __syncthreads();
    if (tid < NN) {
        int pos = atomicAdd(&cursor[tS[tid]], 1);
        rowOrd[pos] = (short)tid;
    }

    // ---- per-segment partial sums (7 segments x 56) ----
    {
        float pP = 0.f, pN = 0.f;
        const int j0 = g * 56;
        for (int j = j0; j < j0 + 56; j++) {
            float v = Vs[(int)sIdx[j] * 64 + o];
            pP = fmaf(ePs[j], v, pP);
            pN = fmaf(eNs[j], v, pN);
        }
        segP[g * 64 + o] = pP;
        segN[g * 64 + o] = pN;
    }
    __syncthreads();

    // ---- segment start states ----
    float Spos = 0.f, Pneg = 0.f;
    {
        float tot = 0.f, sub = 0.f;
#pragma unroll
        for (int gg = 0; gg < 7; gg++) {
            float vP = segP[gg * 64 + o];
            tot += vP;
            if (gg < g) { sub += vP; Pneg += segN[gg * 64 + o]; }
        }
        Spos = tot - sub;
    }

    // ---- sweep: output buckets, update running sums ----
    const float biasO = biasS[o];
    float* outBase = out + (size_t)b * NN * 256 + h * 64 + o;
    const int j0 = g * 56;
    for (int j = j0; j < j0 + 56; j++) {
        for (int rr = base[j]; rr < base[j+1]; rr++) {
            int n = rowOrd[rr];
            float val = wpS[n] * Spos + wnS[n] * Pneg + biasO;
            outBase[(size_t)n * 256] = elu_fast(val);
        }
        float v = Vs[(int)sIdx[j] * 64 + o];
        Pneg = fmaf(eNs[j], v, Pneg);
        Spos = fmaf(-ePs[j], v, Spos);
    }
    if (g == 6) {   // bucket t = 392 (all-negative rows)
        for (int rr = base[NN]; rr < base[NN+1]; rr++) {
            int n = rowOrd[rr];
            float val = wpS[n] * Spos + wnS[n] * Pneg + biasO;
            outBase[(size_t)n * 256] = elu_fast(val);
        }
    }
}

// ---------------------------------------------------------------------------
extern "C" void kernel_launch(void* const* d_in, const int* in_sizes, int n_in,
                              void* d_out, int out_size)
{
    const float* x    = (const float*)d_in[0];   // [B,N,I]
    const float* wml  = (const float*)d_in[2];   // [I,I]
    const float* bml  = (const float*)d_in[3];   // [I]
    const float* ker  = (const float*)d_in[4];   // [I,H,O]
    const float* ask  = (const float*)d_in[5];   // [O,H,1]
    const float* ank  = (const float*)d_in[6];   // [O,H,1]
    const float* bias = (const float*)d_in[7];   // [H*O]
    float* out = (float*)d_out;

    float *p_mlp, *p_xp, *p_mk;
    __nv_bfloat16 *p_bwH, *p_bwM, *p_bkH, *p_bkM;
    cudaGetSymbolAddress((void**)&p_mlp, g_mlp);
    cudaGetSymbolAddress((void**)&p_xp,  g_xp);
    cudaGetSymbolAddress((void**)&p_mk,  g_mk);
    cudaGetSymbolAddress((void**)&p_bwH, g_BwH);
    cudaGetSymbolAddress((void**)&p_bwM, g_BwM);
    cudaGetSymbolAddress((void**)&p_bkH, g_BkH);
    cudaGetSymbolAddress((void**)&p_bkM, g_BkM);

    const int MT = (BNROWS + 63) / 64;           // 662
    const int VSMEM = NN * 64 * sizeof(float);   // 100352
    cudaFuncSetAttribute(attn_sweep, cudaFuncAttributeMaxDynamicSharedMemorySize, VSMEM);

    // 0) split + transpose both weight matrices to [n][k] bf16 hi/lo
    bprep<<<512, 256>>>(wml, ker);

    // 1) mlp = sigmoid(x @ w_mlp + b_mlp)   [mma.sync bf16 3-pass]
    gemm_mma<<<dim3(2, MT), 128>>>(x, p_bwH, p_bwM, bml, p_mlp, BNROWS, 0);

    // 2) APPNP rank-1 (a == ones/N): meanK[b] = (0.8/N * sum_n mlp[b,n]) @ kernel
    mean_meank<<<NB, 512>>>(p_mlp, ker, p_mk);

    // 3) xp = 0.2*(mlp @ kernel) + meanK[b]
    gemm_mma<<<dim3(2, MT), 128>>>(p_mlp, p_bkH, p_bkM, p_mk, p_xp, BNROWS, 3);

    // 4) attention: sorted-threshold sweep (softmax + PV + bias + ELU + s/ng)
    attn_sweep<<<dim3(NH, NB), ATHR, VSMEM>>>(p_xp, ask, ank, bias, out);
}